// round 15
// baseline (speedup 1.0000x reference)
#include <cuda_runtime.h>
#include <cuda_bf16.h>

// Problem shape (fixed by the dataset):
//   x : [16, 512, 64, 64] f32
//   s : [16, 512, 1, 4096] f32
//   z : [16, 1, 512, 1]   f32
//   wq: [1,1,5], wk: [1,1,5], wv: [512,1,3,3]
// Output: out [16,512,64,64], s_new [16,512,1,4096], z_new [16,1,512,1]

#define B 16
#define C 512
#define HW 4096
#define BC (B * C)            // 8192
#define OUT_ELEMS (BC * HW)   // 33554432

__device__ float g_y[BC];

// ---------------------------------------------------------------------------
// Kernel 1: spatial means, 2 planes per block (8 LDG.128 in flight per thread).
// Default cache policy: x allocates in L2; main_kernel (reversed order)
// consumes the MRU tail.
// ---------------------------------------------------------------------------
__global__ void __launch_bounds__(256) mean_kernel(const float* __restrict__ x) {
    int bc0 = blockIdx.x * 2;
    const float4* xpA = reinterpret_cast<const float4*>(x + (size_t)bc0 * HW);
    const float4* xpB = reinterpret_cast<const float4*>(x + (size_t)(bc0 + 1) * HW);
    int t = threadIdx.x;

    float4 va[4], vb[4];
#pragma unroll
    for (int k = 0; k < 4; k++) va[k] = xpA[t + k * 256];
#pragma unroll
    for (int k = 0; k < 4; k++) vb[k] = xpB[t + k * 256];

    float sumA = 0.0f, sumB = 0.0f;
#pragma unroll
    for (int k = 0; k < 4; k++) {
        sumA += (va[k].x + va[k].y) + (va[k].z + va[k].w);
        sumB += (vb[k].x + vb[k].y) + (vb[k].z + vb[k].w);
    }
#pragma unroll
    for (int o = 16; o > 0; o >>= 1) {
        sumA += __shfl_xor_sync(0xffffffffu, sumA, o);
        sumB += __shfl_xor_sync(0xffffffffu, sumB, o);
    }
    __shared__ float ws[16];
    if ((t & 31) == 0) { ws[t >> 5] = sumA; ws[8 + (t >> 5)] = sumB; }
    __syncthreads();
    if (t == 0) {
        float sA = 0.0f, sB = 0.0f;
#pragma unroll
        for (int j = 0; j < 8; j++) { sA += ws[j]; sB += ws[8 + j]; }
        g_y[bc0]     = sA * (1.0f / (float)HW);
        g_y[bc0 + 1] = sB * (1.0f / (float)HW);
    }
}

// ---------------------------------------------------------------------------
// Kernel 2 (fused): Qf/Kf/coef/z_new (thread 0) + depthwise 3x3 conv +
//   s_new = s + Kf*V ; out = coef * s_new
// Reversed block order (L2 MRU-first). Tile layout: pitch 72, x at cols 4..67
// (16B-aligned -> STS.128 scatter), halo cols 3 and 68. Conv reads per row:
// LDS.32 + LDS.128 + LDS.32 (base col0-1).
// ---------------------------------------------------------------------------
#define TP 72   // pitch: x col j -> tile col j+4; (r*72+4)*4 % 16 == 0

__global__ void __launch_bounds__(256)
main_kernel(const float* __restrict__ x,
            const float* __restrict__ s,
            const float* __restrict__ z,
            const float* __restrict__ wq,
            const float* __restrict__ wk,
            const float* __restrict__ wv,
            float* __restrict__ out,
            float* __restrict__ s_new,
            float* __restrict__ z_new) {
    int bc = (BC - 1) - (int)blockIdx.x;   // reversed: consume L2 MRU planes first
    int b = bc >> 9;
    int c = bc & 511;
    size_t base = (size_t)bc * HW;
    int t = threadIdx.x;

    __shared__ __align__(16) float tile[66 * TP];
    __shared__ float sKf, sCf;

    // Front-batched vector loads: 4x x + 4x s = 8 LDG.128 in flight per thread.
    const float4* xp = reinterpret_cast<const float4*>(x + base);
    const float4* sp = reinterpret_cast<const float4*>(s + base);
    float4 xa[4], sv[4];
#pragma unroll
    for (int k = 0; k < 4; k++) xa[k] = __ldcs(xp + t + k * 256);
#pragma unroll
    for (int k = 0; k < 4; k++) sv[k] = __ldcs(sp + t + k * 256);

    // Zero the halo (top/bottom rows cols 3..68; left col 3 / right col 68).
    if (t < 66) { tile[3 + t] = 0.0f; tile[65 * TP + 3 + t] = 0.0f; }
    if (t < 64) { tile[(t + 1) * TP + 3] = 0.0f; tile[(t + 1) * TP + 68] = 0.0f; }

    // Per-channel weights.
    float w[9];
#pragma unroll
    for (int j = 0; j < 9; j++) w[j] = __ldg(wv + c * 9 + j);

    // Thread 0: channel conv (k=5, SAME) -> elu+1 -> Kf, coef, z_new.
    if (t == 0) {
        float q = 0.0f, k = 0.0f;
#pragma unroll
        for (int j = 0; j < 5; j++) {
            int cc = c + j - 2;
            float v = ((unsigned)cc < (unsigned)C) ? g_y[(b << 9) + cc] : 0.0f;
            q += __ldg(wq + j) * v;
            k += __ldg(wk + j) * v;
        }
        float Qf = (q > 0.0f) ? (q + 1.0f) : expf(q);
        float Kf = (k > 0.0f) ? (k + 1.0f) : expf(k);
        float zn = z[bc] + Kf;
        float qz = 1.0f / (Qf * (zn + 1e-6f));
        sKf = Kf;
        sCf = Qf * qz;
        z_new[bc] = zn;
    }

    // Scatter x into the tile with ALIGNED STS.128 (x col j -> tile col j+4).
#pragma unroll
    for (int k = 0; k < 4; k++) {
        int q = t + k * 256;          // float4 index 0..1023
        int p = q << 2;               // pixel
        int r = p >> 6;               // row 0..63
        int col = p & 63;             // col (multiple of 4)
        *reinterpret_cast<float4*>(&tile[(r + 1) * TP + col + 4]) = xa[k];
    }
    __syncthreads();

    float Kf = sKf;
    float Cf = sCf;

    float4* op = reinterpret_cast<float4*>(out + base);
    float4* np = reinterpret_cast<float4*>(s_new + base);

#pragma unroll
    for (int k = 0; k < 4; k++) {
        int q = t + k * 256;
        int p = q << 2;
        int r = p >> 6;
        int col0 = p & 63;

        float a0 = 0.0f, a1 = 0.0f, a2 = 0.0f, a3 = 0.0f;
#pragma unroll
        for (int di = 0; di < 3; di++) {
            // Need x cols col0-1 .. col0+4 = tile cols col0+3 .. col0+8.
            const float* rowp = &tile[(r + di) * TP + col0 + 4];   // 16B-aligned
            float lef = rowp[-1];
            float4 f4 = *reinterpret_cast<const float4*>(rowp);
            float rig = rowp[4];
            float w0 = w[di * 3 + 0], w1 = w[di * 3 + 1], w2 = w[di * 3 + 2];
            a0 = fmaf(w0, lef,  fmaf(w1, f4.x, fmaf(w2, f4.y, a0)));
            a1 = fmaf(w0, f4.x, fmaf(w1, f4.y, fmaf(w2, f4.z, a1)));
            a2 = fmaf(w0, f4.y, fmaf(w1, f4.z, fmaf(w2, f4.w, a2)));
            a3 = fmaf(w0, f4.z, fmaf(w1, f4.w, fmaf(w2, rig,  a3)));
        }

        float4 sn, ov;
        sn.x = sv[k].x + Kf * a0;
        sn.y = sv[k].y + Kf * a1;
        sn.z = sv[k].z + Kf * a2;
        sn.w = sv[k].w + Kf * a3;
        ov.x = Cf * sn.x;
        ov.y = Cf * sn.y;
        ov.z = Cf * sn.z;
        ov.w = Cf * sn.w;
        __stcs(np + q, sn);
        __stcs(op + q, ov);
    }
}

// ---------------------------------------------------------------------------
extern "C" void kernel_launch(void* const* d_in, const int* in_sizes, int n_in,
                              void* d_out, int out_size) {
    const float* x  = (const float*)d_in[0];
    const float* s  = (const float*)d_in[1];
    const float* z  = (const float*)d_in[2];
    const float* wq = (const float*)d_in[3];
    const float* wk = (const float*)d_in[4];
    const float* wv = (const float*)d_in[5];

    float* out   = (float*)d_out;                 // [BC, HW]
    float* s_new = out + (size_t)OUT_ELEMS;       // [BC, HW]
    float* z_new = s_new + (size_t)OUT_ELEMS;     // [BC]

    mean_kernel<<<BC / 2, 256>>>(x);
    main_kernel<<<BC, 256>>>(x, s, z, wq, wk, wv, out, s_new, z_new);
}

// round 16
// speedup vs baseline: 1.3690x; 1.3690x over previous
#include <cuda_runtime.h>
#include <cuda_bf16.h>

// Problem shape (fixed by the dataset):
//   x : [16, 512, 64, 64] f32
//   s : [16, 512, 1, 4096] f32
//   z : [16, 1, 512, 1]   f32
//   wq: [1,1,5], wk: [1,1,5], wv: [512,1,3,3]
// Output: out [16,512,64,64], s_new [16,512,1,4096], z_new [16,1,512,1]

#define B 16
#define C 512
#define HW 4096
#define BC (B * C)            // 8192
#define OUT_ELEMS (BC * HW)   // 33554432

__device__ float g_y[BC];

// ---------------------------------------------------------------------------
// Kernel 1: spatial mean of x per (b,c). Default cache policy so x lands in
// L2 for main_kernel's reversed-order re-read. Each block signals PDL
// completion right after publishing its g_y value.
// ---------------------------------------------------------------------------
__global__ void __launch_bounds__(256) mean_kernel(const float* __restrict__ x) {
    int bc = blockIdx.x;
    const float4* xp = reinterpret_cast<const float4*>(x + (size_t)bc * HW);
    int t = threadIdx.x;
    float sum = 0.0f;
#pragma unroll
    for (int k = 0; k < 4; k++) {
        float4 v = xp[t + k * 256];
        sum += (v.x + v.y) + (v.z + v.w);
    }
#pragma unroll
    for (int o = 16; o > 0; o >>= 1) sum += __shfl_xor_sync(0xffffffffu, sum, o);
    __shared__ float ws[8];
    if ((t & 31) == 0) ws[t >> 5] = sum;
    __syncthreads();
    if (t < 8) {
        float s2 = ws[t];
#pragma unroll
        for (int o = 4; o > 0; o >>= 1) s2 += __shfl_xor_sync(0xffu, s2, o);
        if (t == 0) {
            g_y[bc] = s2 * (1.0f / (float)HW);
            // PDL: this block's externally visible work is done.
            asm volatile("griddepcontrol.launch_dependents;");
        }
    }
}

// ---------------------------------------------------------------------------
// Kernel 2 (fused): Qf/Kf/coef/z_new (thread 0) + depthwise 3x3 conv +
//   s_new = s + Kf*V ; out = coef * s_new
// Launched with programmatic stream serialization (PDL): blocks may start
// while mean_kernel drains; all g_y-independent work (loads, halo, scatter)
// runs first, and only thread 0 waits (griddepcontrol.wait) before reading
// g_y. Exact R5 configuration otherwise (measured best: 79.2us).
// ---------------------------------------------------------------------------
#define TP 68   // tile pitch: 66 rows x 68 floats; (r*68 + col0) % 4 == 0

__global__ void __launch_bounds__(256)
main_kernel(const float* __restrict__ x,
            const float* __restrict__ s,
            const float* __restrict__ z,
            const float* __restrict__ wq,
            const float* __restrict__ wk,
            const float* __restrict__ wv,
            float* __restrict__ out,
            float* __restrict__ s_new,
            float* __restrict__ z_new) {
    int bc = (BC - 1) - (int)blockIdx.x;   // reversed: consume L2 MRU planes first
    int b = bc >> 9;
    int c = bc & 511;
    size_t base = (size_t)bc * HW;
    int t = threadIdx.x;

    __shared__ float tile[66 * TP];
    __shared__ float sKf, sCf;

    // Front-batched vector loads: 4x x + 4x s = 8 LDG.128 in flight per thread.
    const float4* xp = reinterpret_cast<const float4*>(x + base);
    const float4* sp = reinterpret_cast<const float4*>(s + base);
    float4 xa[4], sv[4];
#pragma unroll
    for (int k = 0; k < 4; k++) xa[k] = __ldcs(xp + t + k * 256);
#pragma unroll
    for (int k = 0; k < 4; k++) sv[k] = __ldcs(sp + t + k * 256);

    // Zero the halo ring while loads are in flight.
    if (t < 66) { tile[t] = 0.0f; tile[65 * TP + t] = 0.0f; }
    if (t < 64) { tile[(t + 1) * TP] = 0.0f; tile[(t + 1) * TP + 65] = 0.0f; }

    // Per-channel weights.
    float w[9];
#pragma unroll
    for (int j = 0; j < 9; j++) w[j] = __ldg(wv + c * 9 + j);

    // Scatter x into the haloed tile (no predication, no division).
#pragma unroll
    for (int k = 0; k < 4; k++) {
        int q = t + k * 256;          // float4 index 0..1023
        int p = q << 2;               // pixel
        int r = p >> 6;               // row 0..63
        int col = p & 63;             // col (multiple of 4)
        float* dst = &tile[(r + 1) * TP + col + 1];
        dst[0] = xa[k].x; dst[1] = xa[k].y; dst[2] = xa[k].z; dst[3] = xa[k].w;
    }

    // Thread 0: wait for the producer grid, then channel conv -> coefficients.
    if (t == 0) {
        asm volatile("griddepcontrol.wait;" ::: "memory");
        float q = 0.0f, k = 0.0f;
#pragma unroll
        for (int j = 0; j < 5; j++) {
            int cc = c + j - 2;
            float v = ((unsigned)cc < (unsigned)C) ? g_y[(b << 9) + cc] : 0.0f;
            q += __ldg(wq + j) * v;
            k += __ldg(wk + j) * v;
        }
        float Qf = (q > 0.0f) ? (q + 1.0f) : expf(q);
        float Kf = (k > 0.0f) ? (k + 1.0f) : expf(k);
        float zn = z[bc] + Kf;
        float qz = 1.0f / (Qf * (zn + 1e-6f));
        sKf = Kf;
        sCf = Qf * qz;
        z_new[bc] = zn;
    }
    __syncthreads();

    float Kf = sKf;
    float Cf = sCf;

    float4* op = reinterpret_cast<float4*>(out + base);
    float4* np = reinterpret_cast<float4*>(s_new + base);

#pragma unroll
    for (int k = 0; k < 4; k++) {
        int q = t + k * 256;
        int p = q << 2;
        int r = p >> 6;
        int col0 = p & 63;

        float a0 = 0.0f, a1 = 0.0f, a2 = 0.0f, a3 = 0.0f;
#pragma unroll
        for (int di = 0; di < 3; di++) {
            const float* rowp = &tile[(r + di) * TP + col0];
            float4 f4 = *reinterpret_cast<const float4*>(rowp);      // 16B aligned
            float2 f2 = *reinterpret_cast<const float2*>(rowp + 4);  // 8B aligned
            float w0 = w[di * 3 + 0], w1 = w[di * 3 + 1], w2 = w[di * 3 + 2];
            a0 = fmaf(w0, f4.x, fmaf(w1, f4.y, fmaf(w2, f4.z, a0)));
            a1 = fmaf(w0, f4.y, fmaf(w1, f4.z, fmaf(w2, f4.w, a1)));
            a2 = fmaf(w0, f4.z, fmaf(w1, f4.w, fmaf(w2, f2.x, a2)));
            a3 = fmaf(w0, f4.w, fmaf(w1, f2.x, fmaf(w2, f2.y, a3)));
        }

        float4 sn, ov;
        sn.x = sv[k].x + Kf * a0;
        sn.y = sv[k].y + Kf * a1;
        sn.z = sv[k].z + Kf * a2;
        sn.w = sv[k].w + Kf * a3;
        ov.x = Cf * sn.x;
        ov.y = Cf * sn.y;
        ov.z = Cf * sn.z;
        ov.w = Cf * sn.w;
        __stcs(np + q, sn);
        __stcs(op + q, ov);
    }
}

// ---------------------------------------------------------------------------
extern "C" void kernel_launch(void* const* d_in, const int* in_sizes, int n_in,
                              void* d_out, int out_size) {
    const float* x  = (const float*)d_in[0];
    const float* s  = (const float*)d_in[1];
    const float* z  = (const float*)d_in[2];
    const float* wq = (const float*)d_in[3];
    const float* wk = (const float*)d_in[4];
    const float* wv = (const float*)d_in[5];

    float* out   = (float*)d_out;                 // [BC, HW]
    float* s_new = out + (size_t)OUT_ELEMS;       // [BC, HW]
    float* z_new = s_new + (size_t)OUT_ELEMS;     // [BC]

    mean_kernel<<<BC, 256>>>(x);

    // Launch main_kernel with programmatic dependent launch so its blocks can
    // begin their independent load phase while mean_kernel drains.
    {
        cudaLaunchConfig_t cfg = {};
        cfg.gridDim = dim3(BC, 1, 1);
        cfg.blockDim = dim3(256, 1, 1);
        cfg.dynamicSmemBytes = 0;
        cfg.stream = 0;
        cudaLaunchAttribute attr[1];
        attr[0].id = cudaLaunchAttributeProgrammaticStreamSerialization;
        attr[0].val.programmaticStreamSerializationAllowed = 1;
        cfg.attrs = attr;
        cfg.numAttrs = 1;
        cudaLaunchKernelEx(&cfg, main_kernel, x, s, z, wq, wk, wv,
                           out, s_new, z_new);
    }
}

// round 17
// speedup vs baseline: 1.3703x; 1.0009x over previous
#include <cuda_runtime.h>
#include <cuda_bf16.h>

// Problem shape (fixed by the dataset):
//   x : [16, 512, 64, 64] f32
//   s : [16, 512, 1, 4096] f32
//   z : [16, 1, 512, 1]   f32
//   wq: [1,1,5], wk: [1,1,5], wv: [512,1,3,3]
// Output: out [16,512,64,64], s_new [16,512,1,4096], z_new [16,1,512,1]

#define B 16
#define C 512
#define HW 4096
#define BC (B * C)            // 8192
#define OUT_ELEMS (BC * HW)   // 33554432

__device__ float g_y[BC];

// ---------------------------------------------------------------------------
// Kernel 1: spatial mean of x per (b,c). Default cache policy so x lands in
// L2 for main_kernel's reversed-order re-read.
// PDL both ways:
//  - launched with programmatic stream serialization -> may overlap the
//    PREVIOUS replay's main_kernel drain (safe: mean reads only x, and it
//    cannot launch until every previous main block signaled after consuming
//    g_y).
//  - signals launch_dependents right after publishing g_y so main_kernel can
//    ramp during mean's drain.
// ---------------------------------------------------------------------------
__global__ void __launch_bounds__(256) mean_kernel(const float* __restrict__ x) {
    int bc = blockIdx.x;
    const float4* xp = reinterpret_cast<const float4*>(x + (size_t)bc * HW);
    int t = threadIdx.x;
    float sum = 0.0f;
#pragma unroll
    for (int k = 0; k < 4; k++) {
        float4 v = xp[t + k * 256];
        sum += (v.x + v.y) + (v.z + v.w);
    }
#pragma unroll
    for (int o = 16; o > 0; o >>= 1) sum += __shfl_xor_sync(0xffffffffu, sum, o);
    __shared__ float ws[8];
    if ((t & 31) == 0) ws[t >> 5] = sum;
    __syncthreads();
    if (t < 8) {
        float s2 = ws[t];
#pragma unroll
        for (int o = 4; o > 0; o >>= 1) s2 += __shfl_xor_sync(0xffu, s2, o);
        if (t == 0) {
            g_y[bc] = s2 * (1.0f / (float)HW);
            // This block's externally visible work is done.
            asm volatile("griddepcontrol.launch_dependents;");
        }
    }
}

// ---------------------------------------------------------------------------
// Kernel 2 (fused): Qf/Kf/coef/z_new (thread 0) + depthwise 3x3 conv +
//   s_new = s + Kf*V ; out = coef * s_new
// PDL: blocks start while mean_kernel drains; g_y-independent work first,
// thread 0 waits (griddepcontrol.wait) right before reading g_y, then signals
// launch_dependents (all 5 g_y taps consumed) so the NEXT replay's mean may
// overlap this kernel's drain.
// ---------------------------------------------------------------------------
#define TP 68   // tile pitch: 66 rows x 68 floats; (r*68 + col0) % 4 == 0

__global__ void __launch_bounds__(256)
main_kernel(const float* __restrict__ x,
            const float* __restrict__ s,
            const float* __restrict__ z,
            const float* __restrict__ wq,
            const float* __restrict__ wk,
            const float* __restrict__ wv,
            float* __restrict__ out,
            float* __restrict__ s_new,
            float* __restrict__ z_new) {
    int bc = (BC - 1) - (int)blockIdx.x;   // reversed: consume L2 MRU planes first
    int b = bc >> 9;
    int c = bc & 511;
    size_t base = (size_t)bc * HW;
    int t = threadIdx.x;

    __shared__ float tile[66 * TP];
    __shared__ float sKf, sCf;

    // Front-batched vector loads: 4x x + 4x s = 8 LDG.128 in flight per thread.
    const float4* xp = reinterpret_cast<const float4*>(x + base);
    const float4* sp = reinterpret_cast<const float4*>(s + base);
    float4 xa[4], sv[4];
#pragma unroll
    for (int k = 0; k < 4; k++) xa[k] = __ldcs(xp + t + k * 256);
#pragma unroll
    for (int k = 0; k < 4; k++) sv[k] = __ldcs(sp + t + k * 256);

    // Zero the halo ring while loads are in flight.
    if (t < 66) { tile[t] = 0.0f; tile[65 * TP + t] = 0.0f; }
    if (t < 64) { tile[(t + 1) * TP] = 0.0f; tile[(t + 1) * TP + 65] = 0.0f; }

    // Per-channel weights.
    float w[9];
#pragma unroll
    for (int j = 0; j < 9; j++) w[j] = __ldg(wv + c * 9 + j);

    // Scatter x into the haloed tile (no predication, no division).
#pragma unroll
    for (int k = 0; k < 4; k++) {
        int q = t + k * 256;          // float4 index 0..1023
        int p = q << 2;               // pixel
        int r = p >> 6;               // row 0..63
        int col = p & 63;             // col (multiple of 4)
        float* dst = &tile[(r + 1) * TP + col + 1];
        dst[0] = xa[k].x; dst[1] = xa[k].y; dst[2] = xa[k].z; dst[3] = xa[k].w;
    }

    // Thread 0: wait for producer grid, consume g_y, then signal dependents.
    if (t == 0) {
        asm volatile("griddepcontrol.wait;" ::: "memory");
        float q = 0.0f, k = 0.0f;
#pragma unroll
        for (int j = 0; j < 5; j++) {
            int cc = c + j - 2;
            float v = ((unsigned)cc < (unsigned)C) ? g_y[(b << 9) + cc] : 0.0f;
            q += __ldg(wq + j) * v;
            k += __ldg(wk + j) * v;
        }
        // All g_y reads for this block are done -> next replay's mean may
        // overwrite g_y once every block has reached this point.
        asm volatile("griddepcontrol.launch_dependents;");
        float Qf = (q > 0.0f) ? (q + 1.0f) : expf(q);
        float Kf = (k > 0.0f) ? (k + 1.0f) : expf(k);
        float zn = z[bc] + Kf;
        float qz = 1.0f / (Qf * (zn + 1e-6f));
        sKf = Kf;
        sCf = Qf * qz;
        z_new[bc] = zn;
    }
    __syncthreads();

    float Kf = sKf;
    float Cf = sCf;

    float4* op = reinterpret_cast<float4*>(out + base);
    float4* np = reinterpret_cast<float4*>(s_new + base);

#pragma unroll
    for (int k = 0; k < 4; k++) {
        int q = t + k * 256;
        int p = q << 2;
        int r = p >> 6;
        int col0 = p & 63;

        float a0 = 0.0f, a1 = 0.0f, a2 = 0.0f, a3 = 0.0f;
#pragma unroll
        for (int di = 0; di < 3; di++) {
            const float* rowp = &tile[(r + di) * TP + col0];
            float4 f4 = *reinterpret_cast<const float4*>(rowp);      // 16B aligned
            float2 f2 = *reinterpret_cast<const float2*>(rowp + 4);  // 8B aligned
            float w0 = w[di * 3 + 0], w1 = w[di * 3 + 1], w2 = w[di * 3 + 2];
            a0 = fmaf(w0, f4.x, fmaf(w1, f4.y, fmaf(w2, f4.z, a0)));
            a1 = fmaf(w0, f4.y, fmaf(w1, f4.z, fmaf(w2, f4.w, a1)));
            a2 = fmaf(w0, f4.z, fmaf(w1, f4.w, fmaf(w2, f2.x, a2)));
            a3 = fmaf(w0, f4.w, fmaf(w1, f2.x, fmaf(w2, f2.y, a3)));
        }

        float4 sn, ov;
        sn.x = sv[k].x + Kf * a0;
        sn.y = sv[k].y + Kf * a1;
        sn.z = sv[k].z + Kf * a2;
        sn.w = sv[k].w + Kf * a3;
        ov.x = Cf * sn.x;
        ov.y = Cf * sn.y;
        ov.z = Cf * sn.z;
        ov.w = Cf * sn.w;
        __stcs(np + q, sn);
        __stcs(op + q, ov);
    }
}

// ---------------------------------------------------------------------------
extern "C" void kernel_launch(void* const* d_in, const int* in_sizes, int n_in,
                              void* d_out, int out_size) {
    const float* x  = (const float*)d_in[0];
    const float* s  = (const float*)d_in[1];
    const float* z  = (const float*)d_in[2];
    const float* wq = (const float*)d_in[3];
    const float* wk = (const float*)d_in[4];
    const float* wv = (const float*)d_in[5];

    float* out   = (float*)d_out;                 // [BC, HW]
    float* s_new = out + (size_t)OUT_ELEMS;       // [BC, HW]
    float* z_new = s_new + (size_t)OUT_ELEMS;     // [BC]

    // mean_kernel: PDL-enabled so it can overlap the previous replay's
    // main_kernel drain (mean reads only x; g_y overwrite is gated on every
    // previous main block having signaled after consuming g_y).
    {
        cudaLaunchConfig_t cfg = {};
        cfg.gridDim = dim3(BC, 1, 1);
        cfg.blockDim = dim3(256, 1, 1);
        cfg.dynamicSmemBytes = 0;
        cfg.stream = 0;
        cudaLaunchAttribute attr[1];
        attr[0].id = cudaLaunchAttributeProgrammaticStreamSerialization;
        attr[0].val.programmaticStreamSerializationAllowed = 1;
        cfg.attrs = attr;
        cfg.numAttrs = 1;
        cudaLaunchKernelEx(&cfg, mean_kernel, x);
    }

    // main_kernel: PDL-enabled so its load phase overlaps mean's drain.
    {
        cudaLaunchConfig_t cfg = {};
        cfg.gridDim = dim3(BC, 1, 1);
        cfg.blockDim = dim3(256, 1, 1);
        cfg.dynamicSmemBytes = 0;
        cfg.stream = 0;
        cudaLaunchAttribute attr[1];
        attr[0].id = cudaLaunchAttributeProgrammaticStreamSerialization;
        attr[0].val.programmaticStreamSerializationAllowed = 1;
        cfg.attrs = attr;
        cfg.numAttrs = 1;
        cudaLaunchKernelEx(&cfg, main_kernel, x, s, z, wq, wk, wv,
                           out, s_new, z_new);
    }
}